// round 7
// baseline (speedup 1.0000x reference)
#include <cuda_runtime.h>
#include <stdint.h>

// out[b,t,n,f] = in[b,t,n,f] * ((n < set_size[b,t]) ? (ALPHA+BETA) : 0)
// B=32, T=64, N=128, F=256, fp32.
// ~half the rows masked -> skip input loads there (warp-uniform predicate:
// warp = 32 consecutive f4 = half an F-row).
// Persistent grid-stride: 1184 CTAs (148 SM x 8), each loops ~14 chunks of
// 1024 f4, amortizing CTA prologue and wave transitions.

#define N_DIM 128
#define SCALE 1.1f
#define F4_PER_THREAD 4
#define THREADS 256
#define TOTAL_F4 16777216u
#define CHUNK (THREADS * F4_PER_THREAD)   // 1024 f4 per block-iteration

__global__ void __launch_bounds__(THREADS, 8)
er_mask_scale_kernel(const float4* __restrict__ in,
                     const int* __restrict__ set_size,
                     float4* __restrict__ out)
{
    const unsigned stride = gridDim.x * CHUNK;

    for (unsigned chunk = blockIdx.x * CHUNK; chunk < TOTAL_F4; chunk += stride) {
        unsigned base = chunk + threadIdx.x;

        bool live[F4_PER_THREAD];
        #pragma unroll
        for (int i = 0; i < F4_PER_THREAD; i++) {
            unsigned idx = base + i * THREADS;
            unsigned row = idx >> 6;              // (b,t,n)
            unsigned n   = row & (N_DIM - 1);
            unsigned bt  = row >> 7;
            int ss = __ldg(&set_size[bt]);        // L2-resident broadcast
            live[i] = ((int)n < ss);
        }

        float4 v[F4_PER_THREAD];
        #pragma unroll
        for (int i = 0; i < F4_PER_THREAD; i++) {
            v[i] = make_float4(0.f, 0.f, 0.f, 0.f);
            if (live[i]) v[i] = __ldg(&in[base + i * THREADS]);  // batched
        }

        #pragma unroll
        for (int i = 0; i < F4_PER_THREAD; i++) {
            if (live[i]) {
                v[i].x *= SCALE; v[i].y *= SCALE; v[i].z *= SCALE; v[i].w *= SCALE;
            }
            out[base + i * THREADS] = v[i];
        }
    }
}

extern "C" void kernel_launch(void* const* d_in, const int* in_sizes, int n_in,
                              void* d_out, int out_size)
{
    const float4* in = (const float4*)d_in[0];
    const int* ss = (const int*)d_in[1];
    float4* out = (float4*)d_out;

    const unsigned blocks = 148 * 8;   // 1184 persistent CTAs

    er_mask_scale_kernel<<<blocks, THREADS>>>(in, ss, out);
}

// round 8
// speedup vs baseline: 1.1741x; 1.1741x over previous
#include <cuda_runtime.h>
#include <stdint.h>

// out[b,t,n,f] = in[b,t,n,f] * ((n < set_size[b,t]) ? (ALPHA+BETA) : 0)
// B=32, T=64, N=128, F=256, fp32.
// ~half the rows are zero (set_size ~ U[0,128]) -> skip input load there.
// Empirical optimum (R4): 4 float4/thread, one-shot CTAs, predicates first,
// batched predicated loads (MLP~4), then stores. Warp covers 32 consecutive
// f4 = half an F-row, so the mask predicate is warp-uniform each iteration.
//
// Falsified alternatives: 1 f4/thr (73.8us, MLP-starved), 8 f4/thr (65.8us),
// __ldcs/__stcs (neutral), persistent grid-stride (75.1us, loads serialized
// behind prior-chunk stores). Traffic floor ~343MB @ 6.1TB/s ~= 56us device;
// this kernel runs ~58.5us device / 64us wall.

#define N_DIM 128
#define SCALE 1.1f
#define F4_PER_THREAD 4
#define THREADS 256

// total f4 = 32*64*128*(256/4) = 16,777,216

__global__ void __launch_bounds__(THREADS, 8)
er_mask_scale_kernel(const float4* __restrict__ in,
                     const int* __restrict__ set_size,
                     float4* __restrict__ out)
{
    // block handles 1024 contiguous float4 (= 16 rows of 64 f4)
    unsigned base = blockIdx.x * (THREADS * F4_PER_THREAD) + threadIdx.x;

    unsigned idx[F4_PER_THREAD];
    bool     live[F4_PER_THREAD];

    #pragma unroll
    for (int i = 0; i < F4_PER_THREAD; i++) {
        idx[i] = base + i * THREADS;
        unsigned row = idx[i] >> 6;           // (b,t,n)
        unsigned n   = row & (N_DIM - 1);
        unsigned bt  = row >> 7;
        int ss = __ldg(&set_size[bt]);        // L2-resident broadcast
        live[i] = ((int)n < ss);
    }

    float4 v[F4_PER_THREAD];
    #pragma unroll
    for (int i = 0; i < F4_PER_THREAD; i++) {
        v[i] = make_float4(0.f, 0.f, 0.f, 0.f);
        if (live[i]) v[i] = __ldg(&in[idx[i]]);   // predicated, batched
    }

    #pragma unroll
    for (int i = 0; i < F4_PER_THREAD; i++) {
        if (live[i]) {
            v[i].x *= SCALE; v[i].y *= SCALE; v[i].z *= SCALE; v[i].w *= SCALE;
        }
        out[idx[i]] = v[i];
    }
}

extern "C" void kernel_launch(void* const* d_in, const int* in_sizes, int n_in,
                              void* d_out, int out_size)
{
    const float4* in = (const float4*)d_in[0];
    const int* ss = (const int*)d_in[1];
    float4* out = (float4*)d_out;

    const unsigned total_f4 = 16777216u;
    const unsigned blocks = total_f4 / (THREADS * F4_PER_THREAD); // 16384

    er_mask_scale_kernel<<<blocks, THREADS>>>(in, ss, out);
}

// round 9
// speedup vs baseline: 1.1794x; 1.0045x over previous
#include <cuda_runtime.h>
#include <stdint.h>

// out[b,t,n,f] = in[b,t,n,f] * ((n < set_size[b,t]) ? (ALPHA+BETA) : 0)
// B=32, T=64, N=128, F=256, fp32.
// ~half the rows masked -> skip input loads there.
// Blackwell 256-bit accesses: 2x v8.f32 per thread (64B, same as R4's 4x
// float4) -> half the LDG/STG instructions and L1 wavefronts per byte.
// Warp = 32 consecutive 32B vectors = exactly one F=256 row -> the mask
// predicate is warp-uniform per iteration.

#define N_DIM 128
#define SCALE 1.1f
#define V8_PER_THREAD 2
#define THREADS 256

// total float8 vectors = 32*64*128*(256/8) = 8,388,608
// f8 per (b,t,n) row: 256/8 = 32 -> row = idx >> 5 ; n = row & 127 ; bt = row >> 7

__device__ __forceinline__ void ldg256_nc(const float* p, float v[8])
{
    asm volatile("ld.global.nc.v8.f32 {%0,%1,%2,%3,%4,%5,%6,%7}, [%8];"
                 : "=f"(v[0]), "=f"(v[1]), "=f"(v[2]), "=f"(v[3]),
                   "=f"(v[4]), "=f"(v[5]), "=f"(v[6]), "=f"(v[7])
                 : "l"(p));
}

__device__ __forceinline__ void stg256(float* p, const float v[8])
{
    asm volatile("st.global.v8.f32 [%0], {%1,%2,%3,%4,%5,%6,%7,%8};"
                 :: "l"(p),
                    "f"(v[0]), "f"(v[1]), "f"(v[2]), "f"(v[3]),
                    "f"(v[4]), "f"(v[5]), "f"(v[6]), "f"(v[7])
                 : "memory");
}

__global__ void __launch_bounds__(THREADS, 8)
er_mask_scale_kernel(const float* __restrict__ in,
                     const int* __restrict__ set_size,
                     float* __restrict__ out)
{
    // block handles 512 contiguous f8 (= 16 rows)
    unsigned base = blockIdx.x * (THREADS * V8_PER_THREAD) + threadIdx.x;

    bool live[V8_PER_THREAD];
    #pragma unroll
    for (int i = 0; i < V8_PER_THREAD; i++) {
        unsigned idx = base + i * THREADS;
        unsigned row = idx >> 5;              // (b,t,n)
        unsigned n   = row & (N_DIM - 1);
        unsigned bt  = row >> 7;
        int ss = __ldg(&set_size[bt]);        // L2-resident broadcast
        live[i] = ((int)n < ss);
    }

    float v[V8_PER_THREAD][8];
    #pragma unroll
    for (int i = 0; i < V8_PER_THREAD; i++) {
        #pragma unroll
        for (int j = 0; j < 8; j++) v[i][j] = 0.0f;
        if (live[i]) ldg256_nc(in + (size_t)(base + i * THREADS) * 8, v[i]);
    }

    #pragma unroll
    for (int i = 0; i < V8_PER_THREAD; i++) {
        if (live[i]) {
            #pragma unroll
            for (int j = 0; j < 8; j++) v[i][j] *= SCALE;
        }
        stg256(out + (size_t)(base + i * THREADS) * 8, v[i]);
    }
}

extern "C" void kernel_launch(void* const* d_in, const int* in_sizes, int n_in,
                              void* d_out, int out_size)
{
    const float* in = (const float*)d_in[0];
    const int* ss = (const int*)d_in[1];
    float* out = (float*)d_out;

    const unsigned total_f8 = 8388608u;
    const unsigned blocks = total_f8 / (THREADS * V8_PER_THREAD); // 16384

    er_mask_scale_kernel<<<blocks, THREADS>>>(in, ss, out);
}